// round 1
// baseline (speedup 1.0000x reference)
#include <cuda_runtime.h>
#include <math.h>

#define B_SZ 2
#define L 1024
#define D 384
#define PATCH_DIM 4096
#define DEPTH 12
#define DSTATE 16
#define DTRANK 24
#define DBL_N 56
#define NTOK (B_SZ * L)   // 2048

// ------------------------- scratch (static device) -------------------------
__device__ float g_xp[NTOK * PATCH_DIM];   // 33.5 MB im2col
__device__ float g_tok[NTOK * D];
__device__ float g_h[NTOK * D];
__device__ float g_xz[NTOK * 2 * D];
__device__ float g_xc[NTOK * D];
__device__ float g_dbl[NTOK * DBL_N];
__device__ float g_dt[NTOK * D];
__device__ float g_y[NTOK * D];

// ------------------------- im2col (patch extraction) -----------------------
__global__ void im2col_k(const float* __restrict__ x) {
    int idx = blockIdx.x * blockDim.x + threadIdx.x;   // NTOK*PATCH_DIM threads
    int p  = idx & (PATCH_DIM - 1);
    int bl = idx >> 12;
    int l  = bl & (L - 1);
    int b  = bl >> 10;
    int gh = l >> 6, gw = (l >> 3) & 7, gd = l & 7;
    int ph = p >> 8, pw = (p >> 3) & 31, pd = p & 7;
    int src = ((b * 256 + gh * 16 + ph) * 256 + gw * 32 + pw) * 64 + gd * 8 + pd;
    g_xp[idx] = x[src];
}

// ------------------------- generic SGEMM 64x64 -----------------------------
// C[M,N] = A[M,K(lda)] * B[K,N] (+ epilogue). M is always a multiple of 64.
// epi: 0 = none, 1 = +bias, 2 = +bias then softplus, 3 = C += result
#define BM 64
#define BN 64
#define BK 16

__global__ void sgemm_k(const float* __restrict__ A, int lda,
                        const float* __restrict__ Bmat,
                        float* __restrict__ C,
                        const float* __restrict__ bias,
                        int M, int N, int K, int epi)
{
    __shared__ float As[BK][BM + 4];
    __shared__ float Bs[BK][BN + 4];
    int bm = blockIdx.y * BM, bn = blockIdx.x * BN;
    int tid = threadIdx.x;
    int tx = tid & 15, ty = tid >> 4;
    int am = tid >> 2,  ak  = (tid & 3) << 2;   // A tile: 4 consecutive k per thread
    int bk = tid >> 4,  bn0 = (tid & 15) << 2;  // B tile: 4 consecutive n per thread

    float acc[4][4];
    #pragma unroll
    for (int i = 0; i < 4; i++)
        #pragma unroll
        for (int j = 0; j < 4; j++) acc[i][j] = 0.f;

    for (int k0 = 0; k0 < K; k0 += BK) {
        const float* Ar = A + (long)(bm + am) * lda + k0 + ak;
        #pragma unroll
        for (int i = 0; i < 4; i++) {
            int k = k0 + ak + i;
            As[ak + i][am] = (k < K) ? Ar[i] : 0.f;
        }
        #pragma unroll
        for (int j = 0; j < 4; j++) {
            int n = bn + bn0 + j;
            Bs[bk][bn0 + j] = (k0 + bk < K && n < N) ? Bmat[(long)(k0 + bk) * N + n] : 0.f;
        }
        __syncthreads();
        #pragma unroll
        for (int kk = 0; kk < BK; kk++) {
            float a[4], bb[4];
            #pragma unroll
            for (int i = 0; i < 4; i++) a[i] = As[kk][ty * 4 + i];
            #pragma unroll
            for (int j = 0; j < 4; j++) bb[j] = Bs[kk][tx * 4 + j];
            #pragma unroll
            for (int i = 0; i < 4; i++)
                #pragma unroll
                for (int j = 0; j < 4; j++)
                    acc[i][j] = fmaf(a[i], bb[j], acc[i][j]);
        }
        __syncthreads();
    }

    #pragma unroll
    for (int i = 0; i < 4; i++) {
        int row = bm + ty * 4 + i;
        #pragma unroll
        for (int j = 0; j < 4; j++) {
            int col = bn + tx * 4 + j;
            if (col < N) {
                float v = acc[i][j];
                if (epi == 1 || epi == 2) v += bias[col];
                if (epi == 2) v = (v > 20.f) ? v : log1pf(__expf(v));
                long off = (long)row * N + col;
                if (epi == 3) v += C[off];
                C[off] = v;
            }
        }
    }
}

// ------------------------- LayerNorm (row of 384) --------------------------
__global__ void ln_k(const float* __restrict__ in, float* __restrict__ out,
                     const float* __restrict__ w, const float* __restrict__ b)
{
    int row = blockIdx.x;
    int t = threadIdx.x;   // 128 threads
    const float* r = in + (long)row * D;
    float v0 = r[t], v1 = r[t + 128], v2 = r[t + 256];
    float s = v0 + v1 + v2;
    __shared__ float sh[4], sh2[4];
    #pragma unroll
    for (int o = 16; o; o >>= 1) s += __shfl_xor_sync(~0u, s, o);
    if ((t & 31) == 0) sh[t >> 5] = s;
    __syncthreads();
    float mu = (sh[0] + sh[1] + sh[2] + sh[3]) * (1.f / 384.f);
    float d0 = v0 - mu, d1 = v1 - mu, d2 = v2 - mu;
    float q = d0 * d0 + d1 * d1 + d2 * d2;
    #pragma unroll
    for (int o = 16; o; o >>= 1) q += __shfl_xor_sync(~0u, q, o);
    if ((t & 31) == 0) sh2[t >> 5] = q;
    __syncthreads();
    float var = (sh2[0] + sh2[1] + sh2[2] + sh2[3]) * (1.f / 384.f);
    float rs = rsqrtf(var + 1e-5f);
    float* o = out + (long)row * D;
    o[t]       = d0 * rs * w[t]       + b[t];
    o[t + 128] = d1 * rs * w[t + 128] + b[t + 128];
    o[t + 256] = d2 * rs * w[t + 256] + b[t + 256];
}

// ------------------------- positional embedding ----------------------------
// All maxima are closed-form since batch_params entries are in [0.1, 1.0].
__global__ void posembed_k(const float* __restrict__ bp,
                           const unsigned char* __restrict__ mask)
{
    int row = blockIdx.x;           // NTOK
    int d = threadIdx.x;            // 384
    int b = row >> 10, l = row & 1023;
    int gh = l >> 6, gw = (l >> 3) & 7, gd = l & 7;
    float rr = bp[b * 4 + 0], ar = bp[b * 4 + 1], vr = bp[b * 4 + 2];
    bool m = mask[b] != 0;
    int j = d / 128, r = d - j * 128, f = r & 63;
    float c;
    if (j == 0)      c = ((float)gh * rr) / (15.f * rr);
    else if (j == 1) c = (((float)gw - 4.f) * ar) / (4.f * ar);
    else {
        float v = m ? ((float)gd - 4.f) * vr : (float)gd * vr;
        float den = m ? 4.f * vr : 7.f * vr;
        c = v / den;
    }
    float omega = powf(10000.f, -(float)f * (1.f / 64.f));
    float ph = c * omega;
    g_tok[(long)row * D + d] += (r < 64) ? sinf(ph) : cosf(ph);
}

// ------------------------- causal depthwise conv + silu --------------------
__global__ void conv_k(const float* __restrict__ cw, const float* __restrict__ cb)
{
    int row = blockIdx.x;           // NTOK
    int d = threadIdx.x;            // 384
    int l = row & 1023, b = row >> 10;
    float acc = cb[d];
    #pragma unroll
    for (int j = 0; j < 4; j++) {
        int ll = l - 3 + j;
        if (ll >= 0)
            acc = fmaf(g_xz[(long)((b << 10) + ll) * (2 * D) + d], cw[d * 4 + j], acc);
    }
    g_xc[(long)row * D + d] = acc / (1.f + __expf(-acc));
}

// ------------------------- selective scan -----------------------------------
// One 16-lane group per (b,d) chain; lane = state index n. 48 blocks x 256 thr.
__global__ void scan_k(const float* __restrict__ A_log, const float* __restrict__ Dsk)
{
    int tid = threadIdx.x;
    int g = blockIdx.x * 16 + (tid >> 4);   // 0..767
    int lane = tid & 15;
    int b = g / D;
    int d = g - b * D;

    float Aa = -__expf(A_log[d * DSTATE + lane]);
    float Dp = Dsk[d];
    float h = 0.f;

    const float* dtp = g_dt  + (long)b * L * D + d;
    const float* xcp = g_xc  + (long)b * L * D + d;
    const float* zp  = g_xz  + (long)b * L * (2 * D) + D + d;
    const float* blp = g_dbl + (long)b * L * DBL_N + DTRANK + lane;
    float* yp = g_y + (long)b * L * D + d;

    #pragma unroll 4
    for (int l = 0; l < L; l++) {
        float dtv = dtp[(long)l * D];
        float uv  = xcp[(long)l * D];
        float Bv  = blp[(long)l * DBL_N];
        float Cv  = blp[(long)l * DBL_N + DSTATE];
        float dA  = __expf(dtv * Aa);
        h = fmaf(h, dA, dtv * uv * Bv);
        float p = h * Cv;
        p += __shfl_xor_sync(0xffffffffu, p, 8);
        p += __shfl_xor_sync(0xffffffffu, p, 4);
        p += __shfl_xor_sync(0xffffffffu, p, 2);
        p += __shfl_xor_sync(0xffffffffu, p, 1);
        if (lane == 0) {
            float zv = zp[(long)l * 2 * D];
            float sz = zv / (1.f + __expf(-zv));
            yp[(long)l * D] = (p + uv * Dp) * sz;
        }
    }
}

// ------------------------- launch ------------------------------------------
extern "C" void kernel_launch(void* const* d_in, const int* in_sizes, int n_in,
                              void* d_out, int out_size)
{
    const float* x          = (const float*)d_in[0];
    const float* bp         = (const float*)d_in[1];
    const float* patch_w    = (const float*)d_in[2];
    const float* patch_b    = (const float*)d_in[3];
    const float* in_proj_w  = (const float*)d_in[4];
    const float* conv_w     = (const float*)d_in[5];
    const float* conv_b     = (const float*)d_in[6];
    const float* x_proj_w   = (const float*)d_in[7];
    const float* dt_proj_w  = (const float*)d_in[8];
    const float* dt_proj_b  = (const float*)d_in[9];
    const float* A_log      = (const float*)d_in[10];
    const float* Dskip      = (const float*)d_in[11];
    const float* out_proj_w = (const float*)d_in[12];
    const float* norm_w     = (const float*)d_in[13];
    const float* norm_b     = (const float*)d_in[14];
    const float* fw         = (const float*)d_in[15];
    const float* fb         = (const float*)d_in[16];
    const unsigned char* mask = (const unsigned char*)d_in[17];

    float *xp, *tok, *h, *xz, *xc, *dbl, *dt, *y;
    cudaGetSymbolAddress((void**)&xp,  g_xp);
    cudaGetSymbolAddress((void**)&tok, g_tok);
    cudaGetSymbolAddress((void**)&h,   g_h);
    cudaGetSymbolAddress((void**)&xz,  g_xz);
    cudaGetSymbolAddress((void**)&xc,  g_xc);
    cudaGetSymbolAddress((void**)&dbl, g_dbl);
    cudaGetSymbolAddress((void**)&dt,  g_dt);
    cudaGetSymbolAddress((void**)&y,   g_y);

    // patchify
    im2col_k<<<(NTOK * PATCH_DIM) / 256, 256>>>(x);
    sgemm_k<<<dim3(D / 64, NTOK / 64), 256>>>(xp, PATCH_DIM, patch_w, tok, patch_b,
                                              NTOK, D, PATCH_DIM, 1);
    posembed_k<<<NTOK, D>>>(bp, mask);

    for (int layer = 0; layer < DEPTH; layer++) {
        ln_k<<<NTOK, 128>>>(tok, h, norm_w + layer * D, norm_b + layer * D);
        sgemm_k<<<dim3((2 * D) / 64, NTOK / 64), 256>>>(h, D,
                in_proj_w + (long)layer * D * 2 * D, xz, nullptr, NTOK, 2 * D, D, 0);
        conv_k<<<NTOK, D>>>(conv_w + (long)layer * D * 4, conv_b + (long)layer * D);
        sgemm_k<<<dim3(1, NTOK / 64), 256>>>(xc, D,
                x_proj_w + (long)layer * D * DBL_N, dbl, nullptr, NTOK, DBL_N, D, 0);
        sgemm_k<<<dim3(D / 64, NTOK / 64), 256>>>(dbl, DBL_N,
                dt_proj_w + (long)layer * DTRANK * D, dt, dt_proj_b + (long)layer * D,
                NTOK, D, DTRANK, 2);
        scan_k<<<48, 256>>>(A_log + (long)layer * D * DSTATE, Dskip + (long)layer * D);
        sgemm_k<<<dim3(D / 64, NTOK / 64), 256>>>(y, D,
                out_proj_w + (long)layer * D * D, tok, nullptr, NTOK, D, D, 3);
    }

    ln_k<<<NTOK, 128>>>(tok, (float*)d_out, fw, fb);
}

// round 2
// speedup vs baseline: 1.0694x; 1.0694x over previous
#include <cuda_runtime.h>
#include <math.h>
#include <stdint.h>

#define B_SZ 2
#define L 1024
#define D 384
#define PATCH_DIM 4096
#define DEPTH 12
#define DSTATE 16
#define DTRANK 24
#define DBL_N 56
#define NTOK (B_SZ * L)   // 2048

// ------------------------- scratch (static device) -------------------------
__device__ float g_tok[NTOK * D];
__device__ float g_h[NTOK * D];
__device__ float g_xz[NTOK * 2 * D];
__device__ float g_xc[NTOK * D];
__device__ float g_dbl[NTOK * DBL_N];
__device__ float g_dt[NTOK * D];
__device__ float g_y[NTOK * D];

// ------------------------- cp.async helpers --------------------------------
__device__ __forceinline__ void cp_async16(uint32_t dst, const void* src, bool pred) {
    int sz = pred ? 16 : 0;
    asm volatile("cp.async.ca.shared.global [%0], [%1], 16, %2;\n"
                 :: "r"(dst), "l"(src), "r"(sz));
}
__device__ __forceinline__ void cp_commit() {
    asm volatile("cp.async.commit_group;\n");
}
template <int N>
__device__ __forceinline__ void cp_wait() {
    asm volatile("cp.async.wait_group %0;\n" :: "n"(N));
}

// ------------------------- pipelined SGEMM 64x64 ---------------------------
// C[M,N] = A[M,K(lda)] * B[K,N] (+ epilogue).  M multiple of 64, K,N mult of 4.
// epi: 0 none, 1 +bias, 2 +bias->softplus, 3 C += result.
// gridDim.z > 1 => split-K, results accumulated via atomicAdd (epi must be 0).
#define BM 64
#define BN 64
#define BK 16
#define ASTRIDE 20   // padded row stride for A smem (floats)

struct SmemGemm {
    __align__(16) float As[2][BM * ASTRIDE];
    __align__(16) float Bs[2][BK * BN];
};

__global__ void sgemm_k(const float* __restrict__ A, int lda,
                        const float* __restrict__ Bm,
                        float* __restrict__ C,
                        const float* __restrict__ bias,
                        int M, int N, int K, int epi)
{
    __shared__ SmemGemm sm;
    const int bm = blockIdx.y * BM, bn = blockIdx.x * BN;
    const int tid = threadIdx.x;

    // split-K
    const int ksplit = gridDim.z;
    const int kc = K / ksplit;               // guaranteed divisible by caller
    const int kstart = blockIdx.z * kc;
    const int kend = kstart + kc;
    const int niters = (kc + BK - 1) / BK;

    // loader indices
    const int am  = tid >> 2;                 // 0..63
    const int akq = (tid & 3) << 2;           // 0,4,8,12
    const int bkb = tid >> 4;                 // 0..15
    const int bn4 = (tid & 15) << 2;          // 0..60
    const bool bn_ok = (bn + bn4) < N;

    const float* Arow = A + (size_t)(bm + am) * lda;

    uint32_t sAs = (uint32_t)__cvta_generic_to_shared(&sm.As[0][0]);
    uint32_t sBs = (uint32_t)__cvta_generic_to_shared(&sm.Bs[0][0]);

    auto load_stage = [&](int it, int buf) {
        int k0 = kstart + it * BK;
        // A
        {
            int k = k0 + akq;
            bool p = k < kend;
            const float* src = p ? (Arow + k) : A;
            cp_async16(sAs + (buf * BM * ASTRIDE + am * ASTRIDE + akq) * 4, src, p);
        }
        // B
        {
            int k = k0 + bkb;
            bool p = (k < kend) && bn_ok;
            const float* src = p ? (Bm + (size_t)k * N + bn + bn4) : Bm;
            cp_async16(sBs + (buf * BK * BN + bkb * BN + bn4) * 4, src, p);
        }
    };

    const int ty = tid >> 4, tx = tid & 15;
    const int m0 = ty * 4, n0 = tx * 4;

    float acc[4][4];
    #pragma unroll
    for (int i = 0; i < 4; i++)
        #pragma unroll
        for (int j = 0; j < 4; j++) acc[i][j] = 0.f;

    load_stage(0, 0); cp_commit();
    if (niters > 1) load_stage(1, 1);
    cp_commit();

    for (int it = 0; it < niters; it++) {
        cp_wait<1>();
        __syncthreads();
        const int buf = it & 1;
        const float* As = &sm.As[buf][0];
        const float* Bsr = &sm.Bs[buf][0];
        #pragma unroll
        for (int kk = 0; kk < BK; kk++) {
            float a0 = As[(m0 + 0) * ASTRIDE + kk];
            float a1 = As[(m0 + 1) * ASTRIDE + kk];
            float a2 = As[(m0 + 2) * ASTRIDE + kk];
            float a3 = As[(m0 + 3) * ASTRIDE + kk];
            float4 bv = *reinterpret_cast<const float4*>(&Bsr[kk * BN + n0]);
            acc[0][0] = fmaf(a0, bv.x, acc[0][0]); acc[0][1] = fmaf(a0, bv.y, acc[0][1]);
            acc[0][2] = fmaf(a0, bv.z, acc[0][2]); acc[0][3] = fmaf(a0, bv.w, acc[0][3]);
            acc[1][0] = fmaf(a1, bv.x, acc[1][0]); acc[1][1] = fmaf(a1, bv.y, acc[1][1]);
            acc[1][2] = fmaf(a1, bv.z, acc[1][2]); acc[1][3] = fmaf(a1, bv.w, acc[1][3]);
            acc[2][0] = fmaf(a2, bv.x, acc[2][0]); acc[2][1] = fmaf(a2, bv.y, acc[2][1]);
            acc[2][2] = fmaf(a2, bv.z, acc[2][2]); acc[2][3] = fmaf(a2, bv.w, acc[2][3]);
            acc[3][0] = fmaf(a3, bv.x, acc[3][0]); acc[3][1] = fmaf(a3, bv.y, acc[3][1]);
            acc[3][2] = fmaf(a3, bv.z, acc[3][2]); acc[3][3] = fmaf(a3, bv.w, acc[3][3]);
        }
        __syncthreads();
        if (it + 2 < niters) load_stage(it + 2, buf);
        cp_commit();
    }

    #pragma unroll
    for (int i = 0; i < 4; i++) {
        int row = bm + m0 + i;
        #pragma unroll
        for (int j = 0; j < 4; j++) {
            int col = bn + n0 + j;
            if (col < N) {
                float v = acc[i][j];
                size_t off = (size_t)row * N + col;
                if (ksplit > 1) {
                    atomicAdd(&C[off], v);
                } else {
                    if (epi == 1 || epi == 2) v += bias[col];
                    if (epi == 2) v = (v > 20.f) ? v : log1pf(__expf(v));
                    if (epi == 3) v += C[off];
                    C[off] = v;
                }
            }
        }
    }
}

// ------------------------- patchify GEMM (im2col fused) --------------------
// tok[m, n] = sum_k x_patch(m, k) * patch_w[k, n] + patch_b[n]
__global__ void sgemm_patch_k(const float* __restrict__ X,
                              const float* __restrict__ Bm,
                              float* __restrict__ C,
                              const float* __restrict__ bias)
{
    __shared__ SmemGemm sm;
    const int bm = blockIdx.y * BM, bn = blockIdx.x * BN;
    const int tid = threadIdx.x;
    const int N = D, K = PATCH_DIM;
    const int niters = K / BK;

    const int am  = tid >> 2;
    const int akq = (tid & 3) << 2;
    const int bkb = tid >> 4;
    const int bn4 = (tid & 15) << 2;

    // per-thread token decomposition for the A gather
    const int m = bm + am;
    const int b = m >> 10, l = m & 1023;
    const int gh = l >> 6, gw = (l >> 3) & 7, gd = l & 7;
    const size_t xbase = ((size_t)(b * 256 + gh * 16) * 256 + gw * 32) * 64 + gd * 8;

    uint32_t sAs = (uint32_t)__cvta_generic_to_shared(&sm.As[0][0]);
    uint32_t sBs = (uint32_t)__cvta_generic_to_shared(&sm.Bs[0][0]);

    auto load_stage = [&](int it, int buf) {
        int k0 = it * BK;
        {
            int k = k0 + akq;                  // k < 4096 always
            int ph = k >> 8, pw = (k >> 3) & 31, pd = k & 7;
            const float* src = X + xbase + (size_t)ph * 16384 + pw * 64 + pd;
            cp_async16(sAs + (buf * BM * ASTRIDE + am * ASTRIDE + akq) * 4, src, true);
        }
        {
            int k = k0 + bkb;
            const float* src = Bm + (size_t)k * N + bn + bn4;
            cp_async16(sBs + (buf * BK * BN + bkb * BN + bn4) * 4, src, true);
        }
    };

    const int ty = tid >> 4, tx = tid & 15;
    const int m0 = ty * 4, n0 = tx * 4;

    float acc[4][4];
    #pragma unroll
    for (int i = 0; i < 4; i++)
        #pragma unroll
        for (int j = 0; j < 4; j++) acc[i][j] = 0.f;

    load_stage(0, 0); cp_commit();
    load_stage(1, 1); cp_commit();

    for (int it = 0; it < niters; it++) {
        cp_wait<1>();
        __syncthreads();
        const int buf = it & 1;
        const float* As = &sm.As[buf][0];
        const float* Bsr = &sm.Bs[buf][0];
        #pragma unroll
        for (int kk = 0; kk < BK; kk++) {
            float a0 = As[(m0 + 0) * ASTRIDE + kk];
            float a1 = As[(m0 + 1) * ASTRIDE + kk];
            float a2 = As[(m0 + 2) * ASTRIDE + kk];
            float a3 = As[(m0 + 3) * ASTRIDE + kk];
            float4 bv = *reinterpret_cast<const float4*>(&Bsr[kk * BN + n0]);
            acc[0][0] = fmaf(a0, bv.x, acc[0][0]); acc[0][1] = fmaf(a0, bv.y, acc[0][1]);
            acc[0][2] = fmaf(a0, bv.z, acc[0][2]); acc[0][3] = fmaf(a0, bv.w, acc[0][3]);
            acc[1][0] = fmaf(a1, bv.x, acc[1][0]); acc[1][1] = fmaf(a1, bv.y, acc[1][1]);
            acc[1][2] = fmaf(a1, bv.z, acc[1][2]); acc[1][3] = fmaf(a1, bv.w, acc[1][3]);
            acc[2][0] = fmaf(a2, bv.x, acc[2][0]); acc[2][1] = fmaf(a2, bv.y, acc[2][1]);
            acc[2][2] = fmaf(a2, bv.z, acc[2][2]); acc[2][3] = fmaf(a2, bv.w, acc[2][3]);
            acc[3][0] = fmaf(a3, bv.x, acc[3][0]); acc[3][1] = fmaf(a3, bv.y, acc[3][1]);
            acc[3][2] = fmaf(a3, bv.z, acc[3][2]); acc[3][3] = fmaf(a3, bv.w, acc[3][3]);
        }
        __syncthreads();
        if (it + 2 < niters) load_stage(it + 2, buf);
        cp_commit();
    }

    #pragma unroll
    for (int i = 0; i < 4; i++) {
        int row = bm + m0 + i;
        #pragma unroll
        for (int j = 0; j < 4; j++) {
            int col = bn + n0 + j;
            C[(size_t)row * N + col] = acc[i][j] + bias[col];
        }
    }
}

// ------------------------- zero buffer --------------------------------------
__global__ void zero_k(float* __restrict__ p, int n) {
    int i = blockIdx.x * blockDim.x + threadIdx.x;
    if (i < n) p[i] = 0.f;
}

// ------------------------- LayerNorm (row of 384) --------------------------
__global__ void ln_k(const float* __restrict__ in, float* __restrict__ out,
                     const float* __restrict__ w, const float* __restrict__ b)
{
    int row = blockIdx.x;
    int t = threadIdx.x;   // 128 threads
    const float* r = in + (size_t)row * D;
    float v0 = r[t], v1 = r[t + 128], v2 = r[t + 256];
    float s = v0 + v1 + v2;
    __shared__ float sh[4], sh2[4];
    #pragma unroll
    for (int o = 16; o; o >>= 1) s += __shfl_xor_sync(~0u, s, o);
    if ((t & 31) == 0) sh[t >> 5] = s;
    __syncthreads();
    float mu = (sh[0] + sh[1] + sh[2] + sh[3]) * (1.f / 384.f);
    float d0 = v0 - mu, d1 = v1 - mu, d2 = v2 - mu;
    float q = d0 * d0 + d1 * d1 + d2 * d2;
    #pragma unroll
    for (int o = 16; o; o >>= 1) q += __shfl_xor_sync(~0u, q, o);
    if ((t & 31) == 0) sh2[t >> 5] = q;
    __syncthreads();
    float var = (sh2[0] + sh2[1] + sh2[2] + sh2[3]) * (1.f / 384.f);
    float rs = rsqrtf(var + 1e-5f);
    float* o = out + (size_t)row * D;
    o[t]       = d0 * rs * w[t]       + b[t];
    o[t + 128] = d1 * rs * w[t + 128] + b[t + 128];
    o[t + 256] = d2 * rs * w[t + 256] + b[t + 256];
}

// ------------------------- positional embedding ----------------------------
__global__ void posembed_k(const float* __restrict__ bp,
                           const unsigned char* __restrict__ mask)
{
    int row = blockIdx.x;           // NTOK
    int d = threadIdx.x;            // 384
    int b = row >> 10, l = row & 1023;
    int gh = l >> 6, gw = (l >> 3) & 7, gd = l & 7;
    float vr = bp[b * 4 + 2];
    bool m = mask[b] != 0;
    int j = d / 128, r = d - j * 128, f = r & 63;
    float c;
    if (j == 0)      c = (float)gh * (1.f / 15.f);
    else if (j == 1) c = ((float)gw - 4.f) * 0.25f;
    else {
        float v = m ? ((float)gd - 4.f) * vr : (float)gd * vr;
        float den = m ? 4.f * vr : 7.f * vr;
        c = v / den;
    }
    float omega = powf(10000.f, -(float)f * (1.f / 64.f));
    float ph = c * omega;
    g_tok[(size_t)row * D + d] += (r < 64) ? sinf(ph) : cosf(ph);
}

// ------------------------- causal depthwise conv + silu --------------------
__global__ void conv_k(const float* __restrict__ cw, const float* __restrict__ cb)
{
    int row = blockIdx.x;           // NTOK
    int d = threadIdx.x;            // 384
    int l = row & 1023, b = row >> 10;
    float acc = cb[d];
    #pragma unroll
    for (int j = 0; j < 4; j++) {
        int ll = l - 3 + j;
        if (ll >= 0)
            acc = fmaf(g_xz[(size_t)((b << 10) + ll) * (2 * D) + d], cw[d * 4 + j], acc);
    }
    g_xc[(size_t)row * D + d] = acc / (1.f + __expf(-acc));
}

// ------------------------- selective scan -----------------------------------
// 16 lanes per (b,d) chain, 8 chains per 128-thread block, 96 blocks.
__global__ void scan_k(const float* __restrict__ A_log, const float* __restrict__ Dsk)
{
    int tid = threadIdx.x;
    int g = blockIdx.x * 8 + (tid >> 4);   // 0..767
    int lane = tid & 15;
    int b = g / D;
    int d = g - b * D;

    float Aa = -__expf(A_log[d * DSTATE + lane]);
    float Dp = Dsk[d];
    float h = 0.f;

    const float* dtp = g_dt  + (size_t)b * L * D + d;
    const float* xcp = g_xc  + (size_t)b * L * D + d;
    const float* zp  = g_xz  + (size_t)b * L * (2 * D) + D + d;
    const float* blp = g_dbl + (size_t)b * L * DBL_N + DTRANK + lane;
    float* yp = g_y + (size_t)b * L * D + d;

    #pragma unroll 4
    for (int l = 0; l < L; l++) {
        float dtv = dtp[(size_t)l * D];
        float uv  = xcp[(size_t)l * D];
        float Bv  = blp[(size_t)l * DBL_N];
        float Cv  = blp[(size_t)l * DBL_N + DSTATE];
        float dA  = __expf(dtv * Aa);
        h = fmaf(h, dA, dtv * uv * Bv);
        float p = h * Cv;
        p += __shfl_xor_sync(0xffffffffu, p, 8);
        p += __shfl_xor_sync(0xffffffffu, p, 4);
        p += __shfl_xor_sync(0xffffffffu, p, 2);
        p += __shfl_xor_sync(0xffffffffu, p, 1);
        if (lane == 0) {
            float zv = zp[(size_t)l * 2 * D];
            float sz = zv / (1.f + __expf(-zv));
            yp[(size_t)l * D] = (p + uv * Dp) * sz;
        }
    }
}

// ------------------------- launch ------------------------------------------
extern "C" void kernel_launch(void* const* d_in, const int* in_sizes, int n_in,
                              void* d_out, int out_size)
{
    const float* x          = (const float*)d_in[0];
    const float* bp         = (const float*)d_in[1];
    const float* patch_w    = (const float*)d_in[2];
    const float* patch_b    = (const float*)d_in[3];
    const float* in_proj_w  = (const float*)d_in[4];
    const float* conv_w     = (const float*)d_in[5];
    const float* conv_b     = (const float*)d_in[6];
    const float* x_proj_w   = (const float*)d_in[7];
    const float* dt_proj_w  = (const float*)d_in[8];
    const float* dt_proj_b  = (const float*)d_in[9];
    const float* A_log      = (const float*)d_in[10];
    const float* Dskip      = (const float*)d_in[11];
    const float* out_proj_w = (const float*)d_in[12];
    const float* norm_w     = (const float*)d_in[13];
    const float* norm_b     = (const float*)d_in[14];
    const float* fw         = (const float*)d_in[15];
    const float* fb         = (const float*)d_in[16];
    const unsigned char* mask = (const unsigned char*)d_in[17];

    float *tok, *h, *xz, *xc, *dbl, *dt, *y;
    cudaGetSymbolAddress((void**)&tok, g_tok);
    cudaGetSymbolAddress((void**)&h,   g_h);
    cudaGetSymbolAddress((void**)&xz,  g_xz);
    cudaGetSymbolAddress((void**)&xc,  g_xc);
    cudaGetSymbolAddress((void**)&dbl, g_dbl);
    cudaGetSymbolAddress((void**)&dt,  g_dt);
    cudaGetSymbolAddress((void**)&y,   g_y);

    // patchify (im2col fused) + positional embedding
    sgemm_patch_k<<<dim3(D / 64, NTOK / 64), 256>>>(x, patch_w, tok, patch_b);
    posembed_k<<<NTOK, D>>>(bp, mask);

    for (int layer = 0; layer < DEPTH; layer++) {
        ln_k<<<NTOK, 128>>>(tok, h, norm_w + layer * D, norm_b + layer * D);
        sgemm_k<<<dim3((2 * D) / 64, NTOK / 64, 1), 256>>>(h, D,
                in_proj_w + (size_t)layer * D * 2 * D, xz, nullptr, NTOK, 2 * D, D, 0);
        conv_k<<<NTOK, D>>>(conv_w + (size_t)layer * D * 4, conv_b + (size_t)layer * D);
        zero_k<<<(NTOK * DBL_N + 255) / 256, 256>>>(dbl, NTOK * DBL_N);
        sgemm_k<<<dim3(1, NTOK / 64, 4), 256>>>(xc, D,
                x_proj_w + (size_t)layer * D * DBL_N, dbl, nullptr, NTOK, DBL_N, D, 0);
        sgemm_k<<<dim3(D / 64, NTOK / 64, 1), 256>>>(dbl, DBL_N,
                dt_proj_w + (size_t)layer * DTRANK * D, dt, dt_proj_b + (size_t)layer * D,
                NTOK, D, DTRANK, 2);
        scan_k<<<96, 128>>>(A_log + (size_t)layer * D * DSTATE, Dskip + (size_t)layer * D);
        sgemm_k<<<dim3(D / 64, NTOK / 64, 1), 256>>>(y, D,
                out_proj_w + (size_t)layer * D * D, tok, nullptr, NTOK, D, D, 3);
    }

    ln_k<<<NTOK, 128>>>(tok, (float*)d_out, fw, fb);
}

// round 3
// speedup vs baseline: 2.8026x; 2.6208x over previous
#include <cuda_runtime.h>
#include <math.h>
#include <stdint.h>

#define B_SZ 2
#define L 1024
#define D 384
#define PATCH_DIM 4096
#define DEPTH 12
#define DSTATE 16
#define DTRANK 24
#define DBL_N 56
#define NTOK (B_SZ * L)   // 2048

// ------------------------- scratch (static device) -------------------------
__device__ float g_tok[NTOK * D];
__device__ float g_h[NTOK * D];
__device__ float g_xz[NTOK * 2 * D];
__device__ float g_xc[NTOK * D];
__device__ float g_dbl[NTOK * DBL_N];
__device__ float g_dt[NTOK * D];
__device__ float g_y[NTOK * D];

// ------------------------- cp.async helpers --------------------------------
__device__ __forceinline__ void cp_async16(uint32_t dst, const void* src, bool pred) {
    int sz = pred ? 16 : 0;
    asm volatile("cp.async.ca.shared.global [%0], [%1], 16, %2;\n"
                 :: "r"(dst), "l"(src), "r"(sz));
}
__device__ __forceinline__ void cp_commit() {
    asm volatile("cp.async.commit_group;\n");
}
template <int N>
__device__ __forceinline__ void cp_wait() {
    asm volatile("cp.async.wait_group %0;\n" :: "n"(N));
}

// ------------------------- pipelined SGEMM 64x64 ---------------------------
#define BM 64
#define BN 64
#define BK 16
#define ASTRIDE 20

struct SmemGemm {
    __align__(16) float As[2][BM * ASTRIDE];
    __align__(16) float Bs[2][BK * BN];
};

__global__ void sgemm_k(const float* __restrict__ A, int lda,
                        const float* __restrict__ Bm,
                        float* __restrict__ C,
                        const float* __restrict__ bias,
                        int M, int N, int K, int epi)
{
    __shared__ SmemGemm sm;
    const int bm = blockIdx.y * BM, bn = blockIdx.x * BN;
    const int tid = threadIdx.x;

    const int ksplit = gridDim.z;
    const int kc = K / ksplit;
    const int kstart = blockIdx.z * kc;
    const int kend = kstart + kc;
    const int niters = (kc + BK - 1) / BK;

    const int am  = tid >> 2;
    const int akq = (tid & 3) << 2;
    const int bkb = tid >> 4;
    const int bn4 = (tid & 15) << 2;
    const bool bn_ok = (bn + bn4) < N;

    const float* Arow = A + (size_t)(bm + am) * lda;

    uint32_t sAs = (uint32_t)__cvta_generic_to_shared(&sm.As[0][0]);
    uint32_t sBs = (uint32_t)__cvta_generic_to_shared(&sm.Bs[0][0]);

    auto load_stage = [&](int it, int buf) {
        int k0 = kstart + it * BK;
        {
            int k = k0 + akq;
            bool p = k < kend;
            const float* src = p ? (Arow + k) : A;
            cp_async16(sAs + (buf * BM * ASTRIDE + am * ASTRIDE + akq) * 4, src, p);
        }
        {
            int k = k0 + bkb;
            bool p = (k < kend) && bn_ok;
            const float* src = p ? (Bm + (size_t)k * N + bn + bn4) : Bm;
            cp_async16(sBs + (buf * BK * BN + bkb * BN + bn4) * 4, src, p);
        }
    };

    const int ty = tid >> 4, tx = tid & 15;
    const int m0 = ty * 4, n0 = tx * 4;

    float acc[4][4];
    #pragma unroll
    for (int i = 0; i < 4; i++)
        #pragma unroll
        for (int j = 0; j < 4; j++) acc[i][j] = 0.f;

    load_stage(0, 0); cp_commit();
    if (niters > 1) load_stage(1, 1);
    cp_commit();

    for (int it = 0; it < niters; it++) {
        cp_wait<1>();
        __syncthreads();
        const int buf = it & 1;
        const float* As = &sm.As[buf][0];
        const float* Bsr = &sm.Bs[buf][0];
        #pragma unroll
        for (int kk = 0; kk < BK; kk++) {
            float a0 = As[(m0 + 0) * ASTRIDE + kk];
            float a1 = As[(m0 + 1) * ASTRIDE + kk];
            float a2 = As[(m0 + 2) * ASTRIDE + kk];
            float a3 = As[(m0 + 3) * ASTRIDE + kk];
            float4 bv = *reinterpret_cast<const float4*>(&Bsr[kk * BN + n0]);
            acc[0][0] = fmaf(a0, bv.x, acc[0][0]); acc[0][1] = fmaf(a0, bv.y, acc[0][1]);
            acc[0][2] = fmaf(a0, bv.z, acc[0][2]); acc[0][3] = fmaf(a0, bv.w, acc[0][3]);
            acc[1][0] = fmaf(a1, bv.x, acc[1][0]); acc[1][1] = fmaf(a1, bv.y, acc[1][1]);
            acc[1][2] = fmaf(a1, bv.z, acc[1][2]); acc[1][3] = fmaf(a1, bv.w, acc[1][3]);
            acc[2][0] = fmaf(a2, bv.x, acc[2][0]); acc[2][1] = fmaf(a2, bv.y, acc[2][1]);
            acc[2][2] = fmaf(a2, bv.z, acc[2][2]); acc[2][3] = fmaf(a2, bv.w, acc[2][3]);
            acc[3][0] = fmaf(a3, bv.x, acc[3][0]); acc[3][1] = fmaf(a3, bv.y, acc[3][1]);
            acc[3][2] = fmaf(a3, bv.z, acc[3][2]); acc[3][3] = fmaf(a3, bv.w, acc[3][3]);
        }
        __syncthreads();
        if (it + 2 < niters) load_stage(it + 2, buf);
        cp_commit();
    }

    #pragma unroll
    for (int i = 0; i < 4; i++) {
        int row = bm + m0 + i;
        #pragma unroll
        for (int j = 0; j < 4; j++) {
            int col = bn + n0 + j;
            if (col < N) {
                float v = acc[i][j];
                size_t off = (size_t)row * N + col;
                if (ksplit > 1) {
                    atomicAdd(&C[off], v);
                } else {
                    if (epi == 1 || epi == 2) v += bias[col];
                    if (epi == 2) v = (v > 20.f) ? v : log1pf(__expf(v));
                    if (epi == 3) v += C[off];
                    C[off] = v;
                }
            }
        }
    }
}

// ------------------------- patchify GEMM (im2col fused) --------------------
__global__ void sgemm_patch_k(const float* __restrict__ X,
                              const float* __restrict__ Bm,
                              float* __restrict__ C,
                              const float* __restrict__ bias)
{
    __shared__ SmemGemm sm;
    const int bm = blockIdx.y * BM, bn = blockIdx.x * BN;
    const int tid = threadIdx.x;
    const int N = D, K = PATCH_DIM;
    const int niters = K / BK;

    const int am  = tid >> 2;
    const int akq = (tid & 3) << 2;
    const int bkb = tid >> 4;
    const int bn4 = (tid & 15) << 2;

    const int m = bm + am;
    const int b = m >> 10, l = m & 1023;
    const int gh = l >> 6, gw = (l >> 3) & 7, gd = l & 7;
    const size_t xbase = ((size_t)(b * 256 + gh * 16) * 256 + gw * 32) * 64 + gd * 8;

    uint32_t sAs = (uint32_t)__cvta_generic_to_shared(&sm.As[0][0]);
    uint32_t sBs = (uint32_t)__cvta_generic_to_shared(&sm.Bs[0][0]);

    auto load_stage = [&](int it, int buf) {
        int k0 = it * BK;
        {
            int k = k0 + akq;
            int ph = k >> 8, pw = (k >> 3) & 31, pd = k & 7;
            const float* src = X + xbase + (size_t)ph * 16384 + pw * 64 + pd;
            cp_async16(sAs + (buf * BM * ASTRIDE + am * ASTRIDE + akq) * 4, src, true);
        }
        {
            int k = k0 + bkb;
            const float* src = Bm + (size_t)k * N + bn + bn4;
            cp_async16(sBs + (buf * BK * BN + bkb * BN + bn4) * 4, src, true);
        }
    };

    const int ty = tid >> 4, tx = tid & 15;
    const int m0 = ty * 4, n0 = tx * 4;

    float acc[4][4];
    #pragma unroll
    for (int i = 0; i < 4; i++)
        #pragma unroll
        for (int j = 0; j < 4; j++) acc[i][j] = 0.f;

    load_stage(0, 0); cp_commit();
    load_stage(1, 1); cp_commit();

    for (int it = 0; it < niters; it++) {
        cp_wait<1>();
        __syncthreads();
        const int buf = it & 1;
        const float* As = &sm.As[buf][0];
        const float* Bsr = &sm.Bs[buf][0];
        #pragma unroll
        for (int kk = 0; kk < BK; kk++) {
            float a0 = As[(m0 + 0) * ASTRIDE + kk];
            float a1 = As[(m0 + 1) * ASTRIDE + kk];
            float a2 = As[(m0 + 2) * ASTRIDE + kk];
            float a3 = As[(m0 + 3) * ASTRIDE + kk];
            float4 bv = *reinterpret_cast<const float4*>(&Bsr[kk * BN + n0]);
            acc[0][0] = fmaf(a0, bv.x, acc[0][0]); acc[0][1] = fmaf(a0, bv.y, acc[0][1]);
            acc[0][2] = fmaf(a0, bv.z, acc[0][2]); acc[0][3] = fmaf(a0, bv.w, acc[0][3]);
            acc[1][0] = fmaf(a1, bv.x, acc[1][0]); acc[1][1] = fmaf(a1, bv.y, acc[1][1]);
            acc[1][2] = fmaf(a1, bv.z, acc[1][2]); acc[1][3] = fmaf(a1, bv.w, acc[1][3]);
            acc[2][0] = fmaf(a2, bv.x, acc[2][0]); acc[2][1] = fmaf(a2, bv.y, acc[2][1]);
            acc[2][2] = fmaf(a2, bv.z, acc[2][2]); acc[2][3] = fmaf(a2, bv.w, acc[2][3]);
            acc[3][0] = fmaf(a3, bv.x, acc[3][0]); acc[3][1] = fmaf(a3, bv.y, acc[3][1]);
            acc[3][2] = fmaf(a3, bv.z, acc[3][2]); acc[3][3] = fmaf(a3, bv.w, acc[3][3]);
        }
        __syncthreads();
        if (it + 2 < niters) load_stage(it + 2, buf);
        cp_commit();
    }

    #pragma unroll
    for (int i = 0; i < 4; i++) {
        int row = bm + m0 + i;
        #pragma unroll
        for (int j = 0; j < 4; j++) {
            int col = bn + n0 + j;
            C[(size_t)row * N + col] = acc[i][j] + bias[col];
        }
    }
}

// ------------------------- zero buffer --------------------------------------
__global__ void zero_k(float* __restrict__ p, int n) {
    int i = blockIdx.x * blockDim.x + threadIdx.x;
    if (i < n) p[i] = 0.f;
}

// ------------------------- LayerNorm (row of 384) --------------------------
__global__ void ln_k(const float* __restrict__ in, float* __restrict__ out,
                     const float* __restrict__ w, const float* __restrict__ b)
{
    int row = blockIdx.x;
    int t = threadIdx.x;   // 128 threads
    const float* r = in + (size_t)row * D;
    float v0 = r[t], v1 = r[t + 128], v2 = r[t + 256];
    float s = v0 + v1 + v2;
    __shared__ float sh[4], sh2[4];
    #pragma unroll
    for (int o = 16; o; o >>= 1) s += __shfl_xor_sync(~0u, s, o);
    if ((t & 31) == 0) sh[t >> 5] = s;
    __syncthreads();
    float mu = (sh[0] + sh[1] + sh[2] + sh[3]) * (1.f / 384.f);
    float d0 = v0 - mu, d1 = v1 - mu, d2 = v2 - mu;
    float q = d0 * d0 + d1 * d1 + d2 * d2;
    #pragma unroll
    for (int o = 16; o; o >>= 1) q += __shfl_xor_sync(~0u, q, o);
    if ((t & 31) == 0) sh2[t >> 5] = q;
    __syncthreads();
    float var = (sh2[0] + sh2[1] + sh2[2] + sh2[3]) * (1.f / 384.f);
    float rs = rsqrtf(var + 1e-5f);
    float* o = out + (size_t)row * D;
    o[t]       = d0 * rs * w[t]       + b[t];
    o[t + 128] = d1 * rs * w[t + 128] + b[t + 128];
    o[t + 256] = d2 * rs * w[t + 256] + b[t + 256];
}

// ------------------------- positional embedding ----------------------------
__global__ void posembed_k(const float* __restrict__ bp,
                           const unsigned char* __restrict__ mask)
{
    int row = blockIdx.x;           // NTOK
    int d = threadIdx.x;            // 384
    int b = row >> 10, l = row & 1023;
    int gh = l >> 6, gw = (l >> 3) & 7, gd = l & 7;
    float vr = bp[b * 4 + 2];
    bool m = mask[b] != 0;
    int j = d / 128, r = d - j * 128, f = r & 63;
    float c;
    if (j == 0)      c = (float)gh * (1.f / 15.f);
    else if (j == 1) c = ((float)gw - 4.f) * 0.25f;
    else {
        float v = m ? ((float)gd - 4.f) * vr : (float)gd * vr;
        float den = m ? 4.f * vr : 7.f * vr;
        c = v / den;
    }
    float omega = powf(10000.f, -(float)f * (1.f / 64.f));
    float ph = c * omega;
    g_tok[(size_t)row * D + d] += (r < 64) ? sinf(ph) : cosf(ph);
}

// ------------------------- causal depthwise conv + silu --------------------
__global__ void conv_k(const float* __restrict__ cw, const float* __restrict__ cb)
{
    int row = blockIdx.x;           // NTOK
    int d = threadIdx.x;            // 384
    int l = row & 1023, b = row >> 10;
    float acc = cb[d];
    #pragma unroll
    for (int j = 0; j < 4; j++) {
        int ll = l - 3 + j;
        if (ll >= 0)
            acc = fmaf(g_xz[(size_t)((b << 10) + ll) * (2 * D) + d], cw[d * 4 + j], acc);
    }
    g_xc[(size_t)row * D + d] = acc / (1.f + __expf(-acc));
}

// ------------------------- selective scan (smem-tiled, cp.async) -----------
// 96 blocks x 128 thr. Block = 8 chains of fixed b (blocks 0..47 -> b=0,
// 48..95 -> b=1), chain d = (blk%48)*8 + group. Tiles of 64 steps double-
// buffered through shared memory; B/C are shared across all chains in a block.
#define SCT 64          // tile length (steps)
#define SCH 8           // chains per block

struct ScanSmem {
    __align__(16) float dt[2][SCT][SCH];
    __align__(16) float xc[2][SCT][SCH];
    __align__(16) float zz[2][SCT][SCH];
    __align__(16) float bc[2][SCT][32];   // B[16] | C[16]
};

__global__ void scan_k(const float* __restrict__ A_log, const float* __restrict__ Dsk)
{
    __shared__ ScanSmem sm;
    const int tid = threadIdx.x;          // 128
    const int grp = tid >> 4;             // 0..7
    const int lane = tid & 15;
    const int blk = blockIdx.x;           // 0..95
    const int b = blk / 48;
    const int d0 = (blk % 48) * SCH;      // base d for this block
    const int d = d0 + grp;

    const float Aa = -__expf(A_log[d * DSTATE + lane]);
    const float Dp = Dsk[d];

    const float* dt_g = g_dt  + ((size_t)b * L) * D + d0;
    const float* xc_g = g_xc  + ((size_t)b * L) * D + d0;
    const float* z_g  = g_xz  + ((size_t)b * L) * (2 * D) + D + d0;
    const float* bc_g = g_dbl + ((size_t)b * L) * DBL_N + DTRANK;
    float* y_g = g_y + ((size_t)b * L) * D + d;

    uint32_t s_dt = (uint32_t)__cvta_generic_to_shared(&sm.dt[0][0][0]);
    uint32_t s_xc = (uint32_t)__cvta_generic_to_shared(&sm.xc[0][0][0]);
    uint32_t s_zz = (uint32_t)__cvta_generic_to_shared(&sm.zz[0][0][0]);
    uint32_t s_bc = (uint32_t)__cvta_generic_to_shared(&sm.bc[0][0][0]);

    // loader: thread t handles row i = t>>1, half = t&1 for dt/xc/z (128 txns
    // each), and 4 of the 512 bc transactions (i = q>>3, part = q&7).
    const int li = tid >> 1, lh = (tid & 1) << 2;   // row, float-offset(0/4)

    auto load_tile = [&](int t, int buf) {
        int l0 = t * SCT;
        cp_async16(s_dt + (buf * SCT * SCH + li * SCH + lh) * 4,
                   dt_g + (size_t)(l0 + li) * D + lh, true);
        cp_async16(s_xc + (buf * SCT * SCH + li * SCH + lh) * 4,
                   xc_g + (size_t)(l0 + li) * D + lh, true);
        cp_async16(s_zz + (buf * SCT * SCH + li * SCH + lh) * 4,
                   z_g + (size_t)(l0 + li) * (2 * D) + lh, true);
        #pragma unroll
        for (int q = 0; q < 4; q++) {
            int qq = tid + q * 128;          // 0..511
            int i = qq >> 3, part = (qq & 7) << 2;
            cp_async16(s_bc + (buf * SCT * 32 + i * 32 + part) * 4,
                       bc_g + (size_t)(l0 + i) * DBL_N + part, true);
        }
    };

    load_tile(0, 0);
    cp_commit();

    float h = 0.f;
    const int NT = L / SCT;   // 16

    for (int t = 0; t < NT; t++) {
        if (t + 1 < NT) { load_tile(t + 1, (t + 1) & 1); }
        cp_commit();
        cp_wait<1>();
        __syncthreads();
        const int buf = t & 1;

        #pragma unroll 8
        for (int l = 0; l < SCT; l++) {
            float dtv = sm.dt[buf][l][grp];
            float uv  = sm.xc[buf][l][grp];
            float Bv  = sm.bc[buf][l][lane];
            float Cv  = sm.bc[buf][l][lane + 16];
            float dA  = __expf(dtv * Aa);
            h = fmaf(h, dA, dtv * uv * Bv);
            float p = h * Cv;
            p += __shfl_xor_sync(0xffffffffu, p, 8);
            p += __shfl_xor_sync(0xffffffffu, p, 4);
            p += __shfl_xor_sync(0xffffffffu, p, 2);
            p += __shfl_xor_sync(0xffffffffu, p, 1);
            if (lane == 0) {
                float zv = sm.zz[buf][l][grp];
                float sz = zv / (1.f + __expf(-zv));
                y_g[(size_t)(t * SCT + l) * D] = (p + uv * Dp) * sz;
            }
        }
        __syncthreads();
    }
}

// ------------------------- launch ------------------------------------------
extern "C" void kernel_launch(void* const* d_in, const int* in_sizes, int n_in,
                              void* d_out, int out_size)
{
    const float* x          = (const float*)d_in[0];
    const float* bp         = (const float*)d_in[1];
    const float* patch_w    = (const float*)d_in[2];
    const float* patch_b    = (const float*)d_in[3];
    const float* in_proj_w  = (const float*)d_in[4];
    const float* conv_w     = (const float*)d_in[5];
    const float* conv_b     = (const float*)d_in[6];
    const float* x_proj_w   = (const float*)d_in[7];
    const float* dt_proj_w  = (const float*)d_in[8];
    const float* dt_proj_b  = (const float*)d_in[9];
    const float* A_log      = (const float*)d_in[10];
    const float* Dskip      = (const float*)d_in[11];
    const float* out_proj_w = (const float*)d_in[12];
    const float* norm_w     = (const float*)d_in[13];
    const float* norm_b     = (const float*)d_in[14];
    const float* fw         = (const float*)d_in[15];
    const float* fb         = (const float*)d_in[16];
    const unsigned char* mask = (const unsigned char*)d_in[17];

    float *tok, *h, *xz, *xc, *dbl, *dt, *y;
    cudaGetSymbolAddress((void**)&tok, g_tok);
    cudaGetSymbolAddress((void**)&h,   g_h);
    cudaGetSymbolAddress((void**)&xz,  g_xz);
    cudaGetSymbolAddress((void**)&xc,  g_xc);
    cudaGetSymbolAddress((void**)&dbl, g_dbl);
    cudaGetSymbolAddress((void**)&dt,  g_dt);
    cudaGetSymbolAddress((void**)&y,   g_y);

    sgemm_patch_k<<<dim3(D / 64, NTOK / 64), 256>>>(x, patch_w, tok, patch_b);
    posembed_k<<<NTOK, D>>>(bp, mask);

    for (int layer = 0; layer < DEPTH; layer++) {
        ln_k<<<NTOK, 128>>>(tok, h, norm_w + layer * D, norm_b + layer * D);
        sgemm_k<<<dim3((2 * D) / 64, NTOK / 64, 1), 256>>>(h, D,
                in_proj_w + (size_t)layer * D * 2 * D, xz, nullptr, NTOK, 2 * D, D, 0);
        conv_k<<<NTOK, D>>>(conv_w + (size_t)layer * D * 4, conv_b + (size_t)layer * D);
        zero_k<<<(NTOK * DBL_N + 255) / 256, 256>>>(dbl, NTOK * DBL_N);
        sgemm_k<<<dim3(1, NTOK / 64, 4), 256>>>(xc, D,
                x_proj_w + (size_t)layer * D * DBL_N, dbl, nullptr, NTOK, DBL_N, D, 0);
        sgemm_k<<<dim3(D / 64, NTOK / 64, 1), 256>>>(dbl, DBL_N,
                dt_proj_w + (size_t)layer * DTRANK * D, dt, dt_proj_b + (size_t)layer * D,
                NTOK, D, DTRANK, 2);
        scan_k<<<96, 128>>>(A_log + (size_t)layer * D * DSTATE, Dskip + (size_t)layer * D);
        sgemm_k<<<dim3(D / 64, NTOK / 64, 1), 256>>>(y, D,
                out_proj_w + (size_t)layer * D * D, tok, nullptr, NTOK, D, D, 3);
    }

    ln_k<<<NTOK, 128>>>(tok, (float*)d_out, fw, fb);
}

// round 4
// speedup vs baseline: 3.9718x; 1.4172x over previous
#include <cuda_runtime.h>
#include <math.h>
#include <stdint.h>

#define B_SZ 2
#define L 1024
#define D 384
#define PATCH_DIM 4096
#define DEPTH 12
#define DSTATE 16
#define DTRANK 24
#define DBL_N 56
#define NTOK (B_SZ * L)   // 2048
#define NCH 8             // scan chunks
#define CHL (L / NCH)     // 128 steps per chunk

// ------------------------- scratch (static device) -------------------------
__device__ float g_tok[NTOK * D];
__device__ float g_h[NTOK * D];
__device__ float g_xz[NTOK * 2 * D];
__device__ float g_xc[NTOK * D];
__device__ float g_dbl[NTOK * DBL_N];
__device__ float g_dt[NTOK * D];
__device__ float g_y[NTOK * D];
__device__ float g_P[B_SZ * D * NCH * DSTATE];
__device__ float g_W[B_SZ * D * NCH * DSTATE];

// ------------------------- cp.async helpers --------------------------------
__device__ __forceinline__ void cp_async16(uint32_t dst, const void* src, bool pred) {
    int sz = pred ? 16 : 0;
    asm volatile("cp.async.ca.shared.global [%0], [%1], 16, %2;\n"
                 :: "r"(dst), "l"(src), "r"(sz));
}
__device__ __forceinline__ void cp_commit() {
    asm volatile("cp.async.commit_group;\n");
}
template <int N>
__device__ __forceinline__ void cp_wait() {
    asm volatile("cp.async.wait_group %0;\n" :: "n"(N));
}

// ------------------------- pipelined SGEMM 64x64 ---------------------------
#define BM 64
#define BN 64
#define BK 16
#define ASTRIDE 20

struct SmemGemm {
    __align__(16) float As[2][BM * ASTRIDE];
    __align__(16) float Bs[2][BK * BN];
};

__global__ void sgemm_k(const float* __restrict__ A, int lda,
                        const float* __restrict__ Bm,
                        float* __restrict__ C,
                        const float* __restrict__ bias,
                        int M, int N, int K, int epi)
{
    __shared__ SmemGemm sm;
    const int bm = blockIdx.y * BM, bn = blockIdx.x * BN;
    const int tid = threadIdx.x;

    const int ksplit = gridDim.z;
    const int kc = K / ksplit;
    const int kstart = blockIdx.z * kc;
    const int kend = kstart + kc;
    const int niters = (kc + BK - 1) / BK;

    const int am  = tid >> 2;
    const int akq = (tid & 3) << 2;
    const int bkb = tid >> 4;
    const int bn4 = (tid & 15) << 2;
    const bool bn_ok = (bn + bn4) < N;

    const float* Arow = A + (size_t)(bm + am) * lda;

    uint32_t sAs = (uint32_t)__cvta_generic_to_shared(&sm.As[0][0]);
    uint32_t sBs = (uint32_t)__cvta_generic_to_shared(&sm.Bs[0][0]);

    auto load_stage = [&](int it, int buf) {
        int k0 = kstart + it * BK;
        {
            int k = k0 + akq;
            bool p = k < kend;
            const float* src = p ? (Arow + k) : A;
            cp_async16(sAs + (buf * BM * ASTRIDE + am * ASTRIDE + akq) * 4, src, p);
        }
        {
            int k = k0 + bkb;
            bool p = (k < kend) && bn_ok;
            const float* src = p ? (Bm + (size_t)k * N + bn + bn4) : Bm;
            cp_async16(sBs + (buf * BK * BN + bkb * BN + bn4) * 4, src, p);
        }
    };

    const int ty = tid >> 4, tx = tid & 15;
    const int m0 = ty * 4, n0 = tx * 4;

    float acc[4][4];
    #pragma unroll
    for (int i = 0; i < 4; i++)
        #pragma unroll
        for (int j = 0; j < 4; j++) acc[i][j] = 0.f;

    load_stage(0, 0); cp_commit();
    if (niters > 1) load_stage(1, 1);
    cp_commit();

    for (int it = 0; it < niters; it++) {
        cp_wait<1>();
        __syncthreads();
        const int buf = it & 1;
        const float* As = &sm.As[buf][0];
        const float* Bsr = &sm.Bs[buf][0];
        #pragma unroll
        for (int kk = 0; kk < BK; kk++) {
            float a0 = As[(m0 + 0) * ASTRIDE + kk];
            float a1 = As[(m0 + 1) * ASTRIDE + kk];
            float a2 = As[(m0 + 2) * ASTRIDE + kk];
            float a3 = As[(m0 + 3) * ASTRIDE + kk];
            float4 bv = *reinterpret_cast<const float4*>(&Bsr[kk * BN + n0]);
            acc[0][0] = fmaf(a0, bv.x, acc[0][0]); acc[0][1] = fmaf(a0, bv.y, acc[0][1]);
            acc[0][2] = fmaf(a0, bv.z, acc[0][2]); acc[0][3] = fmaf(a0, bv.w, acc[0][3]);
            acc[1][0] = fmaf(a1, bv.x, acc[1][0]); acc[1][1] = fmaf(a1, bv.y, acc[1][1]);
            acc[1][2] = fmaf(a1, bv.z, acc[1][2]); acc[1][3] = fmaf(a1, bv.w, acc[1][3]);
            acc[2][0] = fmaf(a2, bv.x, acc[2][0]); acc[2][1] = fmaf(a2, bv.y, acc[2][1]);
            acc[2][2] = fmaf(a2, bv.z, acc[2][2]); acc[2][3] = fmaf(a2, bv.w, acc[2][3]);
            acc[3][0] = fmaf(a3, bv.x, acc[3][0]); acc[3][1] = fmaf(a3, bv.y, acc[3][1]);
            acc[3][2] = fmaf(a3, bv.z, acc[3][2]); acc[3][3] = fmaf(a3, bv.w, acc[3][3]);
        }
        __syncthreads();
        if (it + 2 < niters) load_stage(it + 2, buf);
        cp_commit();
    }

    #pragma unroll
    for (int i = 0; i < 4; i++) {
        int row = bm + m0 + i;
        #pragma unroll
        for (int j = 0; j < 4; j++) {
            int col = bn + n0 + j;
            if (col < N) {
                float v = acc[i][j];
                size_t off = (size_t)row * N + col;
                if (ksplit > 1) {
                    atomicAdd(&C[off], v);
                } else {
                    if (epi == 1 || epi == 2) v += bias[col];
                    if (epi == 2) v = (v > 20.f) ? v : log1pf(__expf(v));
                    if (epi == 3) v += C[off];
                    C[off] = v;
                }
            }
        }
    }
}

// ------------------------- patchify GEMM (im2col fused) --------------------
__global__ void sgemm_patch_k(const float* __restrict__ X,
                              const float* __restrict__ Bm,
                              float* __restrict__ C,
                              const float* __restrict__ bias)
{
    __shared__ SmemGemm sm;
    const int bm = blockIdx.y * BM, bn = blockIdx.x * BN;
    const int tid = threadIdx.x;
    const int N = D, K = PATCH_DIM;
    const int niters = K / BK;

    const int am  = tid >> 2;
    const int akq = (tid & 3) << 2;
    const int bkb = tid >> 4;
    const int bn4 = (tid & 15) << 2;

    const int m = bm + am;
    const int b = m >> 10, l = m & 1023;
    const int gh = l >> 6, gw = (l >> 3) & 7, gd = l & 7;
    const size_t xbase = ((size_t)(b * 256 + gh * 16) * 256 + gw * 32) * 64 + gd * 8;

    uint32_t sAs = (uint32_t)__cvta_generic_to_shared(&sm.As[0][0]);
    uint32_t sBs = (uint32_t)__cvta_generic_to_shared(&sm.Bs[0][0]);

    auto load_stage = [&](int it, int buf) {
        int k0 = it * BK;
        {
            int k = k0 + akq;
            int ph = k >> 8, pw = (k >> 3) & 31, pd = k & 7;
            const float* src = X + xbase + (size_t)ph * 16384 + pw * 64 + pd;
            cp_async16(sAs + (buf * BM * ASTRIDE + am * ASTRIDE + akq) * 4, src, true);
        }
        {
            int k = k0 + bkb;
            const float* src = Bm + (size_t)k * N + bn + bn4;
            cp_async16(sBs + (buf * BK * BN + bkb * BN + bn4) * 4, src, true);
        }
    };

    const int ty = tid >> 4, tx = tid & 15;
    const int m0 = ty * 4, n0 = tx * 4;

    float acc[4][4];
    #pragma unroll
    for (int i = 0; i < 4; i++)
        #pragma unroll
        for (int j = 0; j < 4; j++) acc[i][j] = 0.f;

    load_stage(0, 0); cp_commit();
    load_stage(1, 1); cp_commit();

    for (int it = 0; it < niters; it++) {
        cp_wait<1>();
        __syncthreads();
        const int buf = it & 1;
        const float* As = &sm.As[buf][0];
        const float* Bsr = &sm.Bs[buf][0];
        #pragma unroll
        for (int kk = 0; kk < BK; kk++) {
            float a0 = As[(m0 + 0) * ASTRIDE + kk];
            float a1 = As[(m0 + 1) * ASTRIDE + kk];
            float a2 = As[(m0 + 2) * ASTRIDE + kk];
            float a3 = As[(m0 + 3) * ASTRIDE + kk];
            float4 bv = *reinterpret_cast<const float4*>(&Bsr[kk * BN + n0]);
            acc[0][0] = fmaf(a0, bv.x, acc[0][0]); acc[0][1] = fmaf(a0, bv.y, acc[0][1]);
            acc[0][2] = fmaf(a0, bv.z, acc[0][2]); acc[0][3] = fmaf(a0, bv.w, acc[0][3]);
            acc[1][0] = fmaf(a1, bv.x, acc[1][0]); acc[1][1] = fmaf(a1, bv.y, acc[1][1]);
            acc[1][2] = fmaf(a1, bv.z, acc[1][2]); acc[1][3] = fmaf(a1, bv.w, acc[1][3]);
            acc[2][0] = fmaf(a2, bv.x, acc[2][0]); acc[2][1] = fmaf(a2, bv.y, acc[2][1]);
            acc[2][2] = fmaf(a2, bv.z, acc[2][2]); acc[2][3] = fmaf(a2, bv.w, acc[2][3]);
            acc[3][0] = fmaf(a3, bv.x, acc[3][0]); acc[3][1] = fmaf(a3, bv.y, acc[3][1]);
            acc[3][2] = fmaf(a3, bv.z, acc[3][2]); acc[3][3] = fmaf(a3, bv.w, acc[3][3]);
        }
        __syncthreads();
        if (it + 2 < niters) load_stage(it + 2, buf);
        cp_commit();
    }

    #pragma unroll
    for (int i = 0; i < 4; i++) {
        int row = bm + m0 + i;
        #pragma unroll
        for (int j = 0; j < 4; j++) {
            int col = bn + n0 + j;
            C[(size_t)row * N + col] = acc[i][j] + bias[col];
        }
    }
}

// ------------------------- zero buffer --------------------------------------
__global__ void zero_k(float* __restrict__ p, int n) {
    int i = blockIdx.x * blockDim.x + threadIdx.x;
    if (i < n) p[i] = 0.f;
}

// ------------------------- LayerNorm (row of 384) --------------------------
__global__ void ln_k(const float* __restrict__ in, float* __restrict__ out,
                     const float* __restrict__ w, const float* __restrict__ b)
{
    int row = blockIdx.x;
    int t = threadIdx.x;   // 128 threads
    const float* r = in + (size_t)row * D;
    float v0 = r[t], v1 = r[t + 128], v2 = r[t + 256];
    float s = v0 + v1 + v2;
    __shared__ float sh[4], sh2[4];
    #pragma unroll
    for (int o = 16; o; o >>= 1) s += __shfl_xor_sync(~0u, s, o);
    if ((t & 31) == 0) sh[t >> 5] = s;
    __syncthreads();
    float mu = (sh[0] + sh[1] + sh[2] + sh[3]) * (1.f / 384.f);
    float d0 = v0 - mu, d1 = v1 - mu, d2 = v2 - mu;
    float q = d0 * d0 + d1 * d1 + d2 * d2;
    #pragma unroll
    for (int o = 16; o; o >>= 1) q += __shfl_xor_sync(~0u, q, o);
    if ((t & 31) == 0) sh2[t >> 5] = q;
    __syncthreads();
    float var = (sh2[0] + sh2[1] + sh2[2] + sh2[3]) * (1.f / 384.f);
    float rs = rsqrtf(var + 1e-5f);
    float* o = out + (size_t)row * D;
    o[t]       = d0 * rs * w[t]       + b[t];
    o[t + 128] = d1 * rs * w[t + 128] + b[t + 128];
    o[t + 256] = d2 * rs * w[t + 256] + b[t + 256];
}

// ------------------------- positional embedding ----------------------------
__global__ void posembed_k(const float* __restrict__ bp,
                           const unsigned char* __restrict__ mask)
{
    int row = blockIdx.x;           // NTOK
    int d = threadIdx.x;            // 384
    int b = row >> 10, l = row & 1023;
    int gh = l >> 6, gw = (l >> 3) & 7, gd = l & 7;
    float vr = bp[b * 4 + 2];
    bool m = mask[b] != 0;
    int j = d / 128, r = d - j * 128, f = r & 63;
    float c;
    if (j == 0)      c = (float)gh * (1.f / 15.f);
    else if (j == 1) c = ((float)gw - 4.f) * 0.25f;
    else {
        float v = m ? ((float)gd - 4.f) * vr : (float)gd * vr;
        float den = m ? 4.f * vr : 7.f * vr;
        c = v / den;
    }
    float omega = powf(10000.f, -(float)f * (1.f / 64.f));
    float ph = c * omega;
    g_tok[(size_t)row * D + d] += (r < 64) ? sinf(ph) : cosf(ph);
}

// ------------------------- causal depthwise conv + silu --------------------
__global__ void conv_k(const float* __restrict__ cw, const float* __restrict__ cb)
{
    int row = blockIdx.x;           // NTOK
    int d = threadIdx.x;            // 384
    int l = row & 1023, b = row >> 10;
    float acc = cb[d];
    #pragma unroll
    for (int j = 0; j < 4; j++) {
        int ll = l - 3 + j;
        if (ll >= 0)
            acc = fmaf(g_xz[(size_t)((b << 10) + ll) * (2 * D) + d], cw[d * 4 + j], acc);
    }
    g_xc[(size_t)row * D + d] = acc / (1.f + __expf(-acc));
}

// ------------------------- chunked selective scan ---------------------------
// Unit = (chain (b,d), chunk c). 16 lanes per unit, 8 units (chains) per
// 128-thread block. Grid (96, NCH). Pass 1 computes (P = prod dA, W = local
// end state) per chunk with h_start = 0. Pass 2 folds the prefix (<= 7 FMAs
// per lane) and replays the chunk to produce y.
__global__ void scan_part_k(const float* __restrict__ A_log)
{
    const int tid = threadIdx.x;
    const int grp = tid >> 4, lane = tid & 15;
    const int c = blockIdx.y;
    const int blk = blockIdx.x;             // 0..95
    const int b = blk / 48;
    const int d = (blk % 48) * 8 + grp;

    const float Aa = -__expf(A_log[d * DSTATE + lane]);

    const size_t l0 = (size_t)b * L + (size_t)c * CHL;
    const float* dt_g = g_dt + l0 * D + d;
    const float* xc_g = g_xc + l0 * D + d;
    const float* B_g  = g_dbl + l0 * DBL_N + DTRANK + lane;

    float h = 0.f, P = 1.f;
    #pragma unroll 4
    for (int l = 0; l < CHL; l++) {
        float dtv = __ldg(dt_g + (size_t)l * D);
        float uv  = __ldg(xc_g + (size_t)l * D);
        float Bv  = __ldg(B_g + (size_t)l * DBL_N);
        float dA  = __expf(dtv * Aa);
        h = fmaf(h, dA, dtv * uv * Bv);
        P *= dA;
    }
    const int chain = b * D + d;
    g_P[((size_t)chain * NCH + c) * DSTATE + lane] = P;
    g_W[((size_t)chain * NCH + c) * DSTATE + lane] = h;
}

__global__ void scan_full_k(const float* __restrict__ A_log,
                            const float* __restrict__ Dsk)
{
    const int tid = threadIdx.x;
    const int grp = tid >> 4, lane = tid & 15;
    const int c = blockIdx.y;
    const int blk = blockIdx.x;             // 0..95
    const int b = blk / 48;
    const int d = (blk % 48) * 8 + grp;
    const int chain = b * D + d;

    const float Aa = -__expf(A_log[d * DSTATE + lane]);
    const float Dp = Dsk[d];

    // prefix fold: h_start for this chunk
    float h = 0.f;
    const float* Pp = g_P + (size_t)chain * NCH * DSTATE + lane;
    const float* Wp = g_W + (size_t)chain * NCH * DSTATE + lane;
    for (int j = 0; j < c; j++)
        h = fmaf(h, Pp[(size_t)j * DSTATE], Wp[(size_t)j * DSTATE]);

    const size_t l0 = (size_t)b * L + (size_t)c * CHL;
    const float* dt_g = g_dt + l0 * D + d;
    const float* xc_g = g_xc + l0 * D + d;
    const float* z_g  = g_xz + l0 * (2 * D) + D + d;
    const float* B_g  = g_dbl + l0 * DBL_N + DTRANK + lane;
    float* y_g = g_y + l0 * D + d;

    #pragma unroll 4
    for (int l = 0; l < CHL; l++) {
        float dtv = __ldg(dt_g + (size_t)l * D);
        float uv  = __ldg(xc_g + (size_t)l * D);
        float Bv  = __ldg(B_g + (size_t)l * DBL_N);
        float Cv  = __ldg(B_g + (size_t)l * DBL_N + DSTATE);
        float dA  = __expf(dtv * Aa);
        h = fmaf(h, dA, dtv * uv * Bv);
        float p = h * Cv;
        p += __shfl_xor_sync(0xffffffffu, p, 8);
        p += __shfl_xor_sync(0xffffffffu, p, 4);
        p += __shfl_xor_sync(0xffffffffu, p, 2);
        p += __shfl_xor_sync(0xffffffffu, p, 1);
        if (lane == 0) {
            float zv = __ldg(z_g + (size_t)l * 2 * D);
            float sz = zv / (1.f + __expf(-zv));
            y_g[(size_t)l * D] = (p + uv * Dp) * sz;
        }
    }
}

// ------------------------- launch ------------------------------------------
extern "C" void kernel_launch(void* const* d_in, const int* in_sizes, int n_in,
                              void* d_out, int out_size)
{
    const float* x          = (const float*)d_in[0];
    const float* bp         = (const float*)d_in[1];
    const float* patch_w    = (const float*)d_in[2];
    const float* patch_b    = (const float*)d_in[3];
    const float* in_proj_w  = (const float*)d_in[4];
    const float* conv_w     = (const float*)d_in[5];
    const float* conv_b     = (const float*)d_in[6];
    const float* x_proj_w   = (const float*)d_in[7];
    const float* dt_proj_w  = (const float*)d_in[8];
    const float* dt_proj_b  = (const float*)d_in[9];
    const float* A_log      = (const float*)d_in[10];
    const float* Dskip      = (const float*)d_in[11];
    const float* out_proj_w = (const float*)d_in[12];
    const float* norm_w     = (const float*)d_in[13];
    const float* norm_b     = (const float*)d_in[14];
    const float* fw         = (const float*)d_in[15];
    const float* fb         = (const float*)d_in[16];
    const unsigned char* mask = (const unsigned char*)d_in[17];

    float *tok, *h, *xz, *xc, *dbl, *dt, *y;
    cudaGetSymbolAddress((void**)&tok, g_tok);
    cudaGetSymbolAddress((void**)&h,   g_h);
    cudaGetSymbolAddress((void**)&xz,  g_xz);
    cudaGetSymbolAddress((void**)&xc,  g_xc);
    cudaGetSymbolAddress((void**)&dbl, g_dbl);
    cudaGetSymbolAddress((void**)&dt,  g_dt);
    cudaGetSymbolAddress((void**)&y,   g_y);

    sgemm_patch_k<<<dim3(D / 64, NTOK / 64), 256>>>(x, patch_w, tok, patch_b);
    posembed_k<<<NTOK, D>>>(bp, mask);

    for (int layer = 0; layer < DEPTH; layer++) {
        ln_k<<<NTOK, 128>>>(tok, h, norm_w + layer * D, norm_b + layer * D);
        sgemm_k<<<dim3((2 * D) / 64, NTOK / 64, 1), 256>>>(h, D,
                in_proj_w + (size_t)layer * D * 2 * D, xz, nullptr, NTOK, 2 * D, D, 0);
        conv_k<<<NTOK, D>>>(conv_w + (size_t)layer * D * 4, conv_b + (size_t)layer * D);
        zero_k<<<(NTOK * DBL_N + 255) / 256, 256>>>(dbl, NTOK * DBL_N);
        sgemm_k<<<dim3(1, NTOK / 64, 4), 256>>>(xc, D,
                x_proj_w + (size_t)layer * D * DBL_N, dbl, nullptr, NTOK, DBL_N, D, 0);
        sgemm_k<<<dim3(D / 64, NTOK / 64, 1), 256>>>(dbl, DBL_N,
                dt_proj_w + (size_t)layer * DTRANK * D, dt, dt_proj_b + (size_t)layer * D,
                NTOK, D, DTRANK, 2);
        scan_part_k<<<dim3(96, NCH), 128>>>(A_log + (size_t)layer * D * DSTATE);
        scan_full_k<<<dim3(96, NCH), 128>>>(A_log + (size_t)layer * D * DSTATE,
                                            Dskip + (size_t)layer * D);
        sgemm_k<<<dim3(D / 64, NTOK / 64, 1), 256>>>(y, D,
                out_proj_w + (size_t)layer * D * D, tok, nullptr, NTOK, D, D, 3);
    }

    ln_k<<<NTOK, 128>>>(tok, (float*)d_out, fw, fb);
}